// round 5
// baseline (speedup 1.0000x reference)
#include <cuda_runtime.h>
#include <cuda_bf16.h>
#include <cstdint>

#define DIM    2048
#define NROWS  16384   // 4 * 4096

// GEMM tiling
#define BM 256
#define BN 128
#define BK 64
#define NKT 64                 // effective K = 4096 (hi half then lo half)
#define GTHREADS 512
#define ABYTES (BM * BK * 2)   // 32768
#define BBYTES (BN * BK * 2)   // 16384
#define STAGE  (ABYTES + BBYTES)
#define GEMM_SMEM (2 * STAGE)  // 98304

// ---------------------------------------------------------------------------
// Scratch (static __device__ globals — allocation-free per harness rules)
// ---------------------------------------------------------------------------
__device__ float          g_wpart[256];
__device__ float          g_wscale;
__device__ float          g_B1[DIM * DIM];                 // fwht_rows(ternary(W))
__device__ __nv_bfloat16  g_Bh[DIM * DIM];                 // hi half of Mt[o][d]
__device__ __nv_bfloat16  g_Bl[DIM * DIM];                 // lo half of Mt[o][d]
__device__ __nv_bfloat16  g_Xq[(size_t)NROWS * DIM];       // x_int exact in bf16
__device__ float          g_rowscale[NROWS];               // x_scale / 7

// ---------------------------------------------------------------------------
// Helpers
// ---------------------------------------------------------------------------
static __device__ __forceinline__ uint32_t smem_u32(const void* p) {
    uint32_t a;
    asm("{ .reg .u64 t; cvta.to.shared.u64 t, %1; cvt.u32.u64 %0, t; }"
        : "=r"(a) : "l"(p));
    return a;
}

static __device__ __forceinline__ void cp_async16(uint32_t dst, const void* src) {
    asm volatile("cp.async.cg.shared.global [%0], [%1], 16;" :: "r"(dst), "l"(src));
}

static __device__ __forceinline__ void ldmatrix_x4(uint32_t* r, uint32_t addr) {
    asm volatile("ldmatrix.sync.aligned.m8n8.x4.shared.b16 {%0,%1,%2,%3}, [%4];"
                 : "=r"(r[0]), "=r"(r[1]), "=r"(r[2]), "=r"(r[3]) : "r"(addr));
}

static __device__ __forceinline__ void ldmatrix_x2(uint32_t* r, uint32_t addr) {
    asm volatile("ldmatrix.sync.aligned.m8n8.x2.shared.b16 {%0,%1}, [%2];"
                 : "=r"(r[0]), "=r"(r[1]) : "r"(addr));
}

static __device__ __forceinline__ void mma_bf16(float* c, const uint32_t* a, const uint32_t* b) {
    asm volatile(
        "mma.sync.aligned.m16n8k16.row.col.f32.bf16.bf16.f32 "
        "{%0,%1,%2,%3}, {%4,%5,%6,%7}, {%8,%9}, {%0,%1,%2,%3};"
        : "+f"(c[0]), "+f"(c[1]), "+f"(c[2]), "+f"(c[3])
        : "r"(a[0]), "r"(a[1]), "r"(a[2]), "r"(a[3]), "r"(b[0]), "r"(b[1]));
}

// ---------------------------------------------------------------------------
// Block reductions (deterministic fixed-order trees)
// ---------------------------------------------------------------------------
static __device__ __forceinline__ float block_sum256(float v, float* red) {
    #pragma unroll
    for (int o = 16; o; o >>= 1) v += __shfl_xor_sync(0xFFFFFFFFu, v, o);
    if ((threadIdx.x & 31) == 0) red[threadIdx.x >> 5] = v;
    __syncthreads();
    float t = red[0];
    #pragma unroll
    for (int w = 1; w < 8; w++) t += red[w];
    __syncthreads();
    return t;
}

static __device__ __forceinline__ float block_max256(float v, float* red) {
    #pragma unroll
    for (int o = 16; o; o >>= 1) v = fmaxf(v, __shfl_xor_sync(0xFFFFFFFFu, v, o));
    if ((threadIdx.x & 31) == 0) red[threadIdx.x >> 5] = v;
    __syncthreads();
    float t = red[0];
    #pragma unroll
    for (int w = 1; w < 8; w++) t = fmaxf(t, red[w]);
    __syncthreads();
    return t;
}

// ---------------------------------------------------------------------------
// K0: mean(|W|) -> g_wscale
// ---------------------------------------------------------------------------
__global__ void k_wabs_part(const float* __restrict__ W) {
    float s = 0.f;
    for (int i = blockIdx.x * 256 + threadIdx.x; i < DIM * DIM; i += 256 * 256)
        s += fabsf(W[i]);
    #pragma unroll
    for (int o = 16; o; o >>= 1) s += __shfl_xor_sync(0xFFFFFFFFu, s, o);
    __shared__ float red[8];
    if ((threadIdx.x & 31) == 0) red[threadIdx.x >> 5] = s;
    __syncthreads();
    if (threadIdx.x == 0) {
        float t = 0.f;
        #pragma unroll
        for (int w = 0; w < 8; w++) t += red[w];
        g_wpart[blockIdx.x] = t;
    }
}

__global__ void k_wabs_fin() {
    float s = g_wpart[threadIdx.x];
    #pragma unroll
    for (int o = 16; o; o >>= 1) s += __shfl_xor_sync(0xFFFFFFFFu, s, o);
    __shared__ float red[8];
    if ((threadIdx.x & 31) == 0) red[threadIdx.x >> 5] = s;
    __syncthreads();
    if (threadIdx.x == 0) {
        float t = 0.f;
        #pragma unroll
        for (int w = 0; w < 8; w++) t += red[w];
        g_wscale = fmaxf(t / (float)(DIM * DIM), 1e-6f);
    }
}

// ---------------------------------------------------------------------------
// K1: ternarize row o of W, FWHT along d, write g_B1[o][d]
// ---------------------------------------------------------------------------
__global__ void k_wq_fwht(const float* __restrict__ W) {
    __shared__ float s[DIM];
    const int o = blockIdx.x;
    const float ws = g_wscale;
    const float th = 0.5f * ws;
    const float* wr = W + (size_t)o * DIM;
    for (int i = threadIdx.x; i < DIM; i += 256) {
        float w = wr[i];
        s[i] = (w > th) ? ws : ((w < -th) ? -ws : 0.f);
    }
    __syncthreads();
    for (int h = 1; h < DIM; h <<= 1) {
        for (int idx = threadIdx.x; idx < DIM / 2; idx += 256) {
            int i = ((idx & ~(h - 1)) << 1) | (idx & (h - 1));
            int j = i + h;
            float a = s[i], b = s[j];
            s[i] = a + b; s[j] = a - b;
        }
        __syncthreads();
    }
    for (int i = threadIdx.x; i < DIM; i += 256)
        g_B1[(size_t)o * DIM + i] = s[i];
}

// ---------------------------------------------------------------------------
// K2: FWHT along axis0 (o) of g_B1, 4 columns per block; split bf16 hi/lo.
//     Result is Mt[o][d], the K-major B operand (already includes w_scale).
// ---------------------------------------------------------------------------
__global__ void k_fwht_cols() {
    __shared__ float s[DIM * 5];   // pad 4 -> 5 against bank conflicts
    const int d0 = blockIdx.x * 4;
    for (int idx = threadIdx.x; idx < DIM * 4; idx += 256) {
        int o = idx >> 2, d = idx & 3;
        s[o * 5 + d] = g_B1[(size_t)o * DIM + d0 + d];
    }
    __syncthreads();
    for (int h = 1; h < DIM; h <<= 1) {
        for (int idx = threadIdx.x; idx < (DIM / 2) * 4; idx += 256) {
            int d = idx & 3, p = idx >> 2;
            int i = ((p & ~(h - 1)) << 1) | (p & (h - 1));
            int j = i + h;
            float a = s[i * 5 + d], b = s[j * 5 + d];
            s[i * 5 + d] = a + b; s[j * 5 + d] = a - b;
        }
        __syncthreads();
    }
    for (int idx = threadIdx.x; idx < DIM * 4; idx += 256) {
        int o = idx >> 2, d = idx & 3;
        float v = s[o * 5 + d];
        __nv_bfloat16 hi = __float2bfloat16(v);
        float lo = v - __bfloat162float(hi);
        g_Bh[(size_t)o * DIM + d0 + d] = hi;
        g_Bl[(size_t)o * DIM + d0 + d] = __float2bfloat16(lo);
    }
}

// ---------------------------------------------------------------------------
// K3: LayerNorm + 4-bit symmetric quant per row.
// ---------------------------------------------------------------------------
__global__ void k_ln_quant(const float* __restrict__ x,
                           const float* __restrict__ gamma,
                           const float* __restrict__ beta) {
    __shared__ float red[8];
    const int row = blockIdx.x;
    const float* xr = x + (size_t)row * DIM;
    float v[8];
    float s = 0.f;
    #pragma unroll
    for (int t = 0; t < 8; t++) { v[t] = xr[threadIdx.x + t * 256]; s += v[t]; }
    s = block_sum256(s, red);
    const float mu = s * (1.f / (float)DIM);
    float sq = 0.f;
    #pragma unroll
    for (int t = 0; t < 8; t++) { float c = v[t] - mu; sq += c * c; }
    sq = block_sum256(sq, red);
    const float rstd = rsqrtf(sq * (1.f / (float)DIM) + 1e-5f);
    float mx = 0.f;
    #pragma unroll
    for (int t = 0; t < 8; t++) {
        int j = threadIdx.x + t * 256;
        float xl = (v[t] - mu) * rstd * gamma[j] + beta[j];
        v[t] = xl;
        mx = fmaxf(mx, fabsf(xl));
    }
    mx = block_max256(mx, red);
    const float xs = fmaxf(mx, 1e-6f);
    #pragma unroll
    for (int t = 0; t < 8; t++) {
        float r = rintf(v[t] * 7.0f / xs);   // round-half-even matches jnp.round
        r = fminf(fmaxf(r, -7.f), 7.f);
        g_Xq[(size_t)row * DIM + threadIdx.x + t * 256] = __float2bfloat16(r);
    }
    if (threadIdx.x == 0) g_rowscale[row] = xs * (1.f / 7.f);
}

// ---------------------------------------------------------------------------
// K4: GEMM via mma.sync (HMMA bf16, fp32 accum).
//   out[m][n] = rowscale[m] * sum_{k<4096} A'[m,k] * B'[n,k]
//   where A' = [Xq | Xq], B' = [Bh | Bl] along K.
//   CTA: 256x128, BK=64, 512 threads, 16 warps in 4x4 grid (warp tile 64x32).
// ---------------------------------------------------------------------------
static __device__ __forceinline__ void load_A(uint32_t base, const __nv_bfloat16* gA,
                                              int ksrc, int tid) {
    #pragma unroll
    for (int i = 0; i < 4; i++) {
        int idx = tid + i * GTHREADS;
        int r = idx >> 3, c = idx & 7;
        uint32_t so = (uint32_t)(r * 128 + ((c ^ (r & 7)) << 4));
        cp_async16(base + so, (const char*)(gA + (size_t)r * DIM + ksrc) + c * 16);
    }
}

static __device__ __forceinline__ void load_B(uint32_t base, const __nv_bfloat16* gB,
                                              int tid) {
    #pragma unroll
    for (int i = 0; i < 2; i++) {
        int idx = tid + i * GTHREADS;
        int r = idx >> 3, c = idx & 7;
        uint32_t so = (uint32_t)(r * 128 + ((c ^ (r & 7)) << 4));
        cp_async16(base + so, (const char*)(gB + (size_t)r * DIM) + c * 16);
    }
}

__global__ void __launch_bounds__(GTHREADS, 1)
k_gemm(float* __restrict__ out) {
    extern __shared__ char smem[];
    const uint32_t sb = smem_u32(smem);
    const int tid  = threadIdx.x;
    const int lane = tid & 31;
    const int wid  = tid >> 5;
    const int wm   = (wid >> 2) * 64;     // warp m-offset in CTA tile
    const int wn   = (wid & 3) * 32;      // warp n-offset
    const int mBase = blockIdx.x * BM;
    const int nBase = blockIdx.y * BN;

    const __nv_bfloat16* gA  = g_Xq + (size_t)mBase * DIM;
    const __nv_bfloat16* gBh = g_Bh + (size_t)nBase * DIM;
    const __nv_bfloat16* gBl = g_Bl + (size_t)nBase * DIM;

    float acc[4][4][4];
    #pragma unroll
    for (int i = 0; i < 4; i++)
        #pragma unroll
        for (int j = 0; j < 4; j++)
            #pragma unroll
            for (int q = 0; q < 4; q++) acc[i][j][q] = 0.f;

    // Prologue: stage 0 <- kt 0
    load_A(sb, gA, 0, tid);
    load_B(sb + ABYTES, gBh, tid);
    asm volatile("cp.async.commit_group;" ::: "memory");

    for (int kt = 0; kt < NKT; kt++) {
        const int b = kt & 1;
        if (kt + 1 < NKT) {
            const int k2 = kt + 1;
            const uint32_t nb = sb + (k2 & 1) * STAGE;
            load_A(nb, gA, (k2 & 31) * BK, tid);
            const __nv_bfloat16* src = (k2 < 32) ? (gBh + k2 * BK)
                                                 : (gBl + (k2 - 32) * BK);
            load_B(nb + ABYTES, src, tid);
            asm volatile("cp.async.commit_group;" ::: "memory");
            asm volatile("cp.async.wait_group 1;" ::: "memory");
        } else {
            asm volatile("cp.async.wait_group 0;" ::: "memory");
        }
        __syncthreads();

        const uint32_t aB = sb + b * STAGE;
        const uint32_t bB = aB + ABYTES;

        #pragma unroll
        for (int ks = 0; ks < 4; ks++) {
            uint32_t af[4][4], bf[4][2];
            #pragma unroll
            for (int im = 0; im < 4; im++) {
                int r = wm + im * 16 + (lane & 15);
                uint32_t chunk = (uint32_t)((ks * 2 + (lane >> 4)) ^ (r & 7));
                ldmatrix_x4(af[im], aB + r * 128 + (chunk << 4));
            }
            #pragma unroll
            for (int in = 0; in < 4; in++) {
                int r = wn + in * 8 + (lane & 7);
                uint32_t chunk = (uint32_t)((ks * 2 + ((lane >> 3) & 1)) ^ (r & 7));
                ldmatrix_x2(bf[in], bB + r * 128 + (chunk << 4));
            }
            #pragma unroll
            for (int im = 0; im < 4; im++)
                #pragma unroll
                for (int in = 0; in < 4; in++)
                    mma_bf16(acc[im][in], af[im], bf[in]);
        }
        __syncthreads();
    }

    // Epilogue: d frag -> (row = tid/4 [+8], col = 2*(tid%4) [+1])
    #pragma unroll
    for (int im = 0; im < 4; im++) {
        const int r0 = mBase + wm + im * 16 + (lane >> 2);
        const int r1 = r0 + 8;
        const float s0 = g_rowscale[r0];
        const float s1 = g_rowscale[r1];
        #pragma unroll
        for (int in = 0; in < 4; in++) {
            const int col = nBase + wn + in * 8 + (lane & 3) * 2;
            float2 v0 = make_float2(acc[im][in][0] * s0, acc[im][in][1] * s0);
            float2 v1 = make_float2(acc[im][in][2] * s1, acc[im][in][3] * s1);
            *reinterpret_cast<float2*>(out + (size_t)r0 * DIM + col) = v0;
            *reinterpret_cast<float2*>(out + (size_t)r1 * DIM + col) = v1;
        }
    }
}

// ---------------------------------------------------------------------------
// Launcher
// ---------------------------------------------------------------------------
extern "C" void kernel_launch(void* const* d_in, const int* in_sizes, int n_in,
                              void* d_out, int out_size) {
    const float* x     = (const float*)d_in[0];
    const float* W     = (const float*)d_in[1];
    const float* gamma = (const float*)d_in[2];
    const float* beta  = (const float*)d_in[3];
    float* out = (float*)d_out;

    static int smem_set = 0;
    if (!smem_set) {
        cudaFuncSetAttribute(k_gemm, cudaFuncAttributeMaxDynamicSharedMemorySize,
                             GEMM_SMEM);
        smem_set = 1;
    }

    k_wabs_part<<<256, 256>>>(W);
    k_wabs_fin<<<1, 256>>>();
    k_wq_fwht<<<DIM, 256>>>(W);
    k_fwht_cols<<<DIM / 4, 256>>>();
    k_ln_quant<<<NROWS, 256>>>(x, gamma, beta);

    dim3 grid(NROWS / BM, DIM / BN);
    k_gemm<<<grid, GTHREADS, GEMM_SMEM>>>(out);
}

// round 6
// speedup vs baseline: 1.7796x; 1.7796x over previous
#include <cuda_runtime.h>
#include <cuda_fp16.h>
#include <cstdint>

#define DIM    2048
#define NROWS  16384   // 4 * 4096

// GEMM tiling (single fp16 pass, K = 2048)
#define BM 256
#define BN 128
#define BK 64
#define NKT 32
#define GTHREADS 512
#define ABYTES (BM * BK * 2)   // 32768
#define BBYTES (BN * BK * 2)   // 16384
#define STAGE  (ABYTES + BBYTES)     // 49152
#define NSTAGE 3
#define GEMM_SMEM (NSTAGE * STAGE)   // 147456

// ---------------------------------------------------------------------------
// Scratch (static __device__ globals — allocation-free per harness rules)
// ---------------------------------------------------------------------------
__device__ float   g_wpart[256];
__device__ float   g_wscale;
__device__ float   g_B1[DIM * DIM];            // fwht_rows(ternary(W))
__device__ __half  g_Bq[DIM * DIM];            // fp16 Mt[o][d]  (K-major B operand)
__device__ __half  g_Xq[(size_t)NROWS * DIM];  // x_int exact in fp16
__device__ float   g_rowscale[NROWS];          // x_scale / 7

// ---------------------------------------------------------------------------
// Helpers
// ---------------------------------------------------------------------------
static __device__ __forceinline__ uint32_t smem_u32(const void* p) {
    uint32_t a;
    asm("{ .reg .u64 t; cvta.to.shared.u64 t, %1; cvt.u32.u64 %0, t; }"
        : "=r"(a) : "l"(p));
    return a;
}

static __device__ __forceinline__ void cp_async16(uint32_t dst, const void* src) {
    asm volatile("cp.async.cg.shared.global [%0], [%1], 16;" :: "r"(dst), "l"(src));
}

static __device__ __forceinline__ void ldmatrix_x4(uint32_t* r, uint32_t addr) {
    asm volatile("ldmatrix.sync.aligned.m8n8.x4.shared.b16 {%0,%1,%2,%3}, [%4];"
                 : "=r"(r[0]), "=r"(r[1]), "=r"(r[2]), "=r"(r[3]) : "r"(addr));
}

static __device__ __forceinline__ void ldmatrix_x2(uint32_t* r, uint32_t addr) {
    asm volatile("ldmatrix.sync.aligned.m8n8.x2.shared.b16 {%0,%1}, [%2];"
                 : "=r"(r[0]), "=r"(r[1]) : "r"(addr));
}

static __device__ __forceinline__ void mma_f16(float* c, const uint32_t* a, const uint32_t* b) {
    asm volatile(
        "mma.sync.aligned.m16n8k16.row.col.f32.f16.f16.f32 "
        "{%0,%1,%2,%3}, {%4,%5,%6,%7}, {%8,%9}, {%0,%1,%2,%3};"
        : "+f"(c[0]), "+f"(c[1]), "+f"(c[2]), "+f"(c[3])
        : "r"(a[0]), "r"(a[1]), "r"(a[2]), "r"(a[3]), "r"(b[0]), "r"(b[1]));
}

// ---------------------------------------------------------------------------
// Block reductions (deterministic fixed-order trees)
// ---------------------------------------------------------------------------
static __device__ __forceinline__ float block_sum256(float v, float* red) {
    #pragma unroll
    for (int o = 16; o; o >>= 1) v += __shfl_xor_sync(0xFFFFFFFFu, v, o);
    if ((threadIdx.x & 31) == 0) red[threadIdx.x >> 5] = v;
    __syncthreads();
    float t = red[0];
    #pragma unroll
    for (int w = 1; w < 8; w++) t += red[w];
    __syncthreads();
    return t;
}

static __device__ __forceinline__ float block_max256(float v, float* red) {
    #pragma unroll
    for (int o = 16; o; o >>= 1) v = fmaxf(v, __shfl_xor_sync(0xFFFFFFFFu, v, o));
    if ((threadIdx.x & 31) == 0) red[threadIdx.x >> 5] = v;
    __syncthreads();
    float t = red[0];
    #pragma unroll
    for (int w = 1; w < 8; w++) t = fmaxf(t, red[w]);
    __syncthreads();
    return t;
}

// ---------------------------------------------------------------------------
// K0: mean(|W|) -> g_wscale
// ---------------------------------------------------------------------------
__global__ void k_wabs_part(const float* __restrict__ W) {
    float s = 0.f;
    for (int i = blockIdx.x * 256 + threadIdx.x; i < DIM * DIM; i += 256 * 256)
        s += fabsf(W[i]);
    #pragma unroll
    for (int o = 16; o; o >>= 1) s += __shfl_xor_sync(0xFFFFFFFFu, s, o);
    __shared__ float red[8];
    if ((threadIdx.x & 31) == 0) red[threadIdx.x >> 5] = s;
    __syncthreads();
    if (threadIdx.x == 0) {
        float t = 0.f;
        #pragma unroll
        for (int w = 0; w < 8; w++) t += red[w];
        g_wpart[blockIdx.x] = t;
    }
}

__global__ void k_wabs_fin() {
    float s = g_wpart[threadIdx.x];
    #pragma unroll
    for (int o = 16; o; o >>= 1) s += __shfl_xor_sync(0xFFFFFFFFu, s, o);
    __shared__ float red[8];
    if ((threadIdx.x & 31) == 0) red[threadIdx.x >> 5] = s;
    __syncthreads();
    if (threadIdx.x == 0) {
        float t = 0.f;
        #pragma unroll
        for (int w = 0; w < 8; w++) t += red[w];
        g_wscale = fmaxf(t / (float)(DIM * DIM), 1e-6f);
    }
}

// ---------------------------------------------------------------------------
// K1: ternarize row o of W, FWHT along d, write g_B1[o][d]
// ---------------------------------------------------------------------------
__global__ void k_wq_fwht(const float* __restrict__ W) {
    __shared__ float s[DIM];
    const int o = blockIdx.x;
    const float ws = g_wscale;
    const float th = 0.5f * ws;
    const float* wr = W + (size_t)o * DIM;
    for (int i = threadIdx.x; i < DIM; i += 256) {
        float w = wr[i];
        s[i] = (w > th) ? ws : ((w < -th) ? -ws : 0.f);
    }
    __syncthreads();
    for (int h = 1; h < DIM; h <<= 1) {
        for (int idx = threadIdx.x; idx < DIM / 2; idx += 256) {
            int i = ((idx & ~(h - 1)) << 1) | (idx & (h - 1));
            int j = i + h;
            float a = s[i], b = s[j];
            s[i] = a + b; s[j] = a - b;
        }
        __syncthreads();
    }
    for (int i = threadIdx.x; i < DIM; i += 256)
        g_B1[(size_t)o * DIM + i] = s[i];
}

// ---------------------------------------------------------------------------
// K2: FWHT along axis0 (o) of g_B1, 4 columns per block; round to fp16.
//     Result is Mt[o][d], the K-major B operand (already includes w_scale).
// ---------------------------------------------------------------------------
__global__ void k_fwht_cols() {
    __shared__ float s[DIM * 5];   // pad 4 -> 5 against bank conflicts
    const int d0 = blockIdx.x * 4;
    for (int idx = threadIdx.x; idx < DIM * 4; idx += 256) {
        int o = idx >> 2, d = idx & 3;
        s[o * 5 + d] = g_B1[(size_t)o * DIM + d0 + d];
    }
    __syncthreads();
    for (int h = 1; h < DIM; h <<= 1) {
        for (int idx = threadIdx.x; idx < (DIM / 2) * 4; idx += 256) {
            int d = idx & 3, p = idx >> 2;
            int i = ((p & ~(h - 1)) << 1) | (p & (h - 1));
            int j = i + h;
            float a = s[i * 5 + d], b = s[j * 5 + d];
            s[i * 5 + d] = a + b; s[j * 5 + d] = a - b;
        }
        __syncthreads();
    }
    for (int idx = threadIdx.x; idx < DIM * 4; idx += 256) {
        int o = idx >> 2, d = idx & 3;
        g_Bq[(size_t)o * DIM + d0 + d] = __float2half_rn(s[o * 5 + d]);
    }
}

// ---------------------------------------------------------------------------
// K3: LayerNorm + 4-bit symmetric quant per row (x_int exact in fp16).
// ---------------------------------------------------------------------------
__global__ void k_ln_quant(const float* __restrict__ x,
                           const float* __restrict__ gamma,
                           const float* __restrict__ beta) {
    __shared__ float red[8];
    const int row = blockIdx.x;
    const float* xr = x + (size_t)row * DIM;
    float v[8];
    float s = 0.f;
    #pragma unroll
    for (int t = 0; t < 8; t++) { v[t] = xr[threadIdx.x + t * 256]; s += v[t]; }
    s = block_sum256(s, red);
    const float mu = s * (1.f / (float)DIM);
    float sq = 0.f;
    #pragma unroll
    for (int t = 0; t < 8; t++) { float c = v[t] - mu; sq += c * c; }
    sq = block_sum256(sq, red);
    const float rstd = rsqrtf(sq * (1.f / (float)DIM) + 1e-5f);
    float mx = 0.f;
    #pragma unroll
    for (int t = 0; t < 8; t++) {
        int j = threadIdx.x + t * 256;
        float xl = (v[t] - mu) * rstd * gamma[j] + beta[j];
        v[t] = xl;
        mx = fmaxf(mx, fabsf(xl));
    }
    mx = block_max256(mx, red);
    const float xs = fmaxf(mx, 1e-6f);
    #pragma unroll
    for (int t = 0; t < 8; t++) {
        float r = rintf(v[t] * 7.0f / xs);   // round-half-even matches jnp.round
        r = fminf(fmaxf(r, -7.f), 7.f);
        g_Xq[(size_t)row * DIM + threadIdx.x + t * 256] = __float2half_rn(r);
    }
    if (threadIdx.x == 0) g_rowscale[row] = xs * (1.f / 7.f);
}

// ---------------------------------------------------------------------------
// K4: GEMM via mma.sync (HMMA fp16, fp32 accum).
//   out[m][n] = rowscale[m] * sum_{k<2048} Xq[m,k] * Bq[n,k]
//   CTA: 256x128, BK=64, 512 threads, 16 warps in 4x4 grid (warp tile 64x32).
//   3-stage cp.async ring, one __syncthreads per k-iter.
// ---------------------------------------------------------------------------
static __device__ __forceinline__ void load_A(uint32_t base, const __half* gA,
                                              int ksrc, int tid) {
    #pragma unroll
    for (int i = 0; i < 4; i++) {
        int idx = tid + i * GTHREADS;
        int r = idx >> 3, c = idx & 7;
        uint32_t so = (uint32_t)(r * 128 + ((c ^ (r & 7)) << 4));
        cp_async16(base + so, (const char*)(gA + (size_t)r * DIM + ksrc) + c * 16);
    }
}

static __device__ __forceinline__ void load_B(uint32_t base, const __half* gB,
                                              int ksrc, int tid) {
    #pragma unroll
    for (int i = 0; i < 2; i++) {
        int idx = tid + i * GTHREADS;
        int r = idx >> 3, c = idx & 7;
        uint32_t so = (uint32_t)(r * 128 + ((c ^ (r & 7)) << 4));
        cp_async16(base + so, (const char*)(gB + (size_t)r * DIM + ksrc) + c * 16);
    }
}

__global__ void __launch_bounds__(GTHREADS, 1)
k_gemm(float* __restrict__ out) {
    extern __shared__ char smem[];
    const uint32_t sb = smem_u32(smem);
    const int tid  = threadIdx.x;
    const int lane = tid & 31;
    const int wid  = tid >> 5;
    const int wm   = (wid >> 2) * 64;     // warp m-offset in CTA tile
    const int wn   = (wid & 3) * 32;      // warp n-offset
    const int mBase = blockIdx.x * BM;
    const int nBase = blockIdx.y * BN;

    const __half* gA = g_Xq + (size_t)mBase * DIM;
    const __half* gB = g_Bq + (size_t)nBase * DIM;

    float acc[4][4][4];
    #pragma unroll
    for (int i = 0; i < 4; i++)
        #pragma unroll
        for (int j = 0; j < 4; j++)
            #pragma unroll
            for (int q = 0; q < 4; q++) acc[i][j][q] = 0.f;

    // Prologue: stages 0 and 1 <- kt 0, 1
    load_A(sb, gA, 0, tid);
    load_B(sb + ABYTES, gB, 0, tid);
    asm volatile("cp.async.commit_group;" ::: "memory");
    load_A(sb + STAGE, gA, BK, tid);
    load_B(sb + STAGE + ABYTES, gB, BK, tid);
    asm volatile("cp.async.commit_group;" ::: "memory");

    int stage = 0;
    for (int kt = 0; kt < NKT; kt++) {
        if (kt < NKT - 1) asm volatile("cp.async.wait_group 1;" ::: "memory");
        else              asm volatile("cp.async.wait_group 0;" ::: "memory");
        __syncthreads();

        const uint32_t aB = sb + stage * STAGE;
        const uint32_t bB = aB + ABYTES;

        #pragma unroll
        for (int ks = 0; ks < 4; ks++) {
            uint32_t af[4][4], bf[4][2];
            #pragma unroll
            for (int im = 0; im < 4; im++) {
                int r = wm + im * 16 + (lane & 15);
                uint32_t chunk = (uint32_t)((ks * 2 + (lane >> 4)) ^ (r & 7));
                ldmatrix_x4(af[im], aB + r * 128 + (chunk << 4));
            }
            #pragma unroll
            for (int in = 0; in < 4; in++) {
                int r = wn + in * 8 + (lane & 7);
                uint32_t chunk = (uint32_t)((ks * 2 + ((lane >> 3) & 1)) ^ (r & 7));
                ldmatrix_x2(bf[in], bB + r * 128 + (chunk << 4));
            }
            #pragma unroll
            for (int im = 0; im < 4; im++)
                #pragma unroll
                for (int in = 0; in < 4; in++)
                    mma_f16(acc[im][in], af[im], bf[in]);
        }

        if (kt + 2 < NKT) {
            const int k2 = kt + 2;
            const int st2 = (stage + 2 >= NSTAGE) ? (stage + 2 - NSTAGE) : (stage + 2);
            const uint32_t nb = sb + st2 * STAGE;
            load_A(nb, gA, k2 * BK, tid);
            load_B(nb + ABYTES, gB, k2 * BK, tid);
            asm volatile("cp.async.commit_group;" ::: "memory");
        }
        stage = (stage + 1 == NSTAGE) ? 0 : stage + 1;
    }

    // Epilogue: d frag -> (row = lane/4 [+8], col = 2*(lane%4) [+1])
    #pragma unroll
    for (int im = 0; im < 4; im++) {
        const int r0 = mBase + wm + im * 16 + (lane >> 2);
        const int r1 = r0 + 8;
        const float s0 = g_rowscale[r0];
        const float s1 = g_rowscale[r1];
        #pragma unroll
        for (int in = 0; in < 4; in++) {
            const int col = nBase + wn + in * 8 + (lane & 3) * 2;
            float2 v0 = make_float2(acc[im][in][0] * s0, acc[im][in][1] * s0);
            float2 v1 = make_float2(acc[im][in][2] * s1, acc[im][in][3] * s1);
            *reinterpret_cast<float2*>(out + (size_t)r0 * DIM + col) = v0;
            *reinterpret_cast<float2*>(out + (size_t)r1 * DIM + col) = v1;
        }
    }
}

// ---------------------------------------------------------------------------
// Launcher
// ---------------------------------------------------------------------------
extern "C" void kernel_launch(void* const* d_in, const int* in_sizes, int n_in,
                              void* d_out, int out_size) {
    const float* x     = (const float*)d_in[0];
    const float* W     = (const float*)d_in[1];
    const float* gamma = (const float*)d_in[2];
    const float* beta  = (const float*)d_in[3];
    float* out = (float*)d_out;

    cudaFuncSetAttribute(k_gemm, cudaFuncAttributeMaxDynamicSharedMemorySize,
                         GEMM_SMEM);

    k_wabs_part<<<256, 256>>>(W);
    k_wabs_fin<<<1, 256>>>();
    k_wq_fwht<<<DIM, 256>>>(W);
    k_fwht_cols<<<DIM / 4, 256>>>();
    k_ln_quant<<<NROWS, 256>>>(x, gamma, beta);

    dim3 grid(NROWS / BM, DIM / BN);
    k_gemm<<<grid, GTHREADS, GEMM_SMEM>>>(out);
}